// round 15
// baseline (speedup 1.0000x reference)
#include <cuda_runtime.h>
#include <cuda_fp16.h>
#include <math.h>
#include <stdint.h>

#define NB 16
#define ROWS 16384

// ---------------- device scratch ----------------
__device__ __align__(16) __half g_Hh[(size_t)NB * 128 * ROWS];  // [b][z][row] fp16
__device__ float g_P[NB * 1024];
__device__ float g_part[NB * 32 * 256];
__device__ __align__(16) uint4 g_B1pk[21 * 4 * 4 * 32];  // [ks][wn][g][lane]
__device__ __align__(16) uint4 g_B2pk[16 * 4 * 2 * 32];  // [c][wn][g][lane]

// ---------------- smem layout (bytes), 128-row CTA ----------------
#define C1H 0                            // 128 x 264 halves (pitch 528B) = 67584
#define A1F(bi) (67584 + (bi) * 13056)   // A tile [k48][row128] fp16, pitch 272B
#define STG 0                            // epilogue-2 staging reuses C1: 128 x 272B
#define SMEM_TOTAL 93696

// ---------------- helpers ----------------
__device__ __forceinline__ uint32_t smem_u32(const void* p) {
    uint32_t a;
    asm("{ .reg .u64 t; cvta.to.shared.u64 t, %1; cvt.u32.u64 %0, t; }" : "=r"(a) : "l"(p));
    return a;
}
__device__ __forceinline__ void ldmat4(uint32_t addr, uint32_t r[4]) {
    asm volatile("ldmatrix.sync.aligned.m8n8.x4.shared.b16 {%0,%1,%2,%3}, [%4];"
        : "=r"(r[0]), "=r"(r[1]), "=r"(r[2]), "=r"(r[3]) : "r"(addr) : "memory");
}
__device__ __forceinline__ void ldmat4t(uint32_t addr, uint32_t r[4]) {
    asm volatile("ldmatrix.sync.aligned.m8n8.x4.trans.shared.b16 {%0,%1,%2,%3}, [%4];"
        : "=r"(r[0]), "=r"(r[1]), "=r"(r[2]), "=r"(r[3]) : "r"(addr) : "memory");
}
__device__ __forceinline__ void mma16816(float d[4], const uint32_t a[4],
                                         uint32_t b0, uint32_t b1) {
    asm volatile("mma.sync.aligned.m16n8k16.row.col.f32.f16.f16.f32 "
        "{%0,%1,%2,%3}, {%4,%5,%6,%7}, {%8,%9}, {%0,%1,%2,%3};"
        : "+f"(d[0]), "+f"(d[1]), "+f"(d[2]), "+f"(d[3])
        : "r"(a[0]), "r"(a[1]), "r"(a[2]), "r"(a[3]), "r"(b0), "r"(b1));
}
__device__ __forceinline__ uint32_t packh2(float x, float y) {
    __half2 h = __floats2half2_rn(x, y);
    return *(uint32_t*)&h;
}
__device__ __forceinline__ const float* selsrc(int s, const float* a, const float* b,
                                               const float* c, const float* d) {
    return s == 0 ? a : (s == 1 ? b : (s == 2 ? c : d));
}

// ============================================================
__global__ void dummy_a_kernel() {}
__global__ void dummy_b_kernel() {}

// ============================================================
// prep: pack W1/W2 into per-lane mma B-fragment order.
// ============================================================
__global__ void prep_w_kernel(const float* __restrict__ W1, const float* __restrict__ W2)
{
    int idx = blockIdx.x * 256 + threadIdx.x;
    if (idx < 21 * 4 * 4 * 32) {
        int lane = idx & 31, g = (idx >> 5) & 3, wn = (idx >> 7) & 3, c = idx >> 9;
        int n0 = wn * 64 + (2 * g) * 8 + (lane >> 2);
        int n1 = n0 + 8;
        int kb = c * 16 + 2 * (lane & 3);
        auto f = [&](int k, int n) -> float { return (k < 324) ? W1[k * 256 + n] : 0.f; };
        uint4 v;
        v.x = packh2(f(kb, n0),     f(kb + 1, n0));
        v.y = packh2(f(kb + 8, n0), f(kb + 9, n0));
        v.z = packh2(f(kb, n1),     f(kb + 1, n1));
        v.w = packh2(f(kb + 8, n1), f(kb + 9, n1));
        g_B1pk[idx] = v;
    } else {
        int m = idx - 21 * 4 * 4 * 32;
        if (m < 16 * 4 * 2 * 32) {
            int lane = m & 31, g = (m >> 5) & 1, wn = (m >> 6) & 3, c = m >> 8;
            int n0 = wn * 32 + (2 * g) * 8 + (lane >> 2);
            int n1 = n0 + 8;
            int kb = c * 16 + 2 * (lane & 3);
            uint4 v;
            v.x = packh2(W2[kb * 128 + n0],       W2[(kb + 1) * 128 + n0]);
            v.y = packh2(W2[(kb + 8) * 128 + n0], W2[(kb + 9) * 128 + n0]);
            v.z = packh2(W2[kb * 128 + n1],       W2[(kb + 1) * 128 + n1]);
            v.w = packh2(W2[(kb + 8) * 128 + n1], W2[(kb + 9) * 128 + n1]);
            g_B2pk[m] = v;
        }
    }
}

// ============================================================
// fused GEMM1 -> ReLU -> GEMM2, fp16 MMA
// CTA: 256 threads (2M x 4N warps), 128 rows, 1 CTA/SM. grid (128, 16).
// Warp tile 64m x 64n; register-lean schedule (A-fill halves, A-frag pairs).
// ============================================================
__global__ void __launch_bounds__(256, 1) gemm_mma_kernel(
    const float* __restrict__ fgc, const float* __restrict__ fgt,
    const float* __restrict__ bgc, const float* __restrict__ bgt,
    const float* __restrict__ b1, const float* __restrict__ b2)
{
    extern __shared__ char sm[];
    const uint32_t smb = smem_u32(sm);
    const int tid = threadIdx.x, lane = tid & 31, warp = tid >> 5;
    const int wm = warp & 1, wn = warp >> 1;          // 2 x 4
    const int b = blockIdx.y;
    const int row0 = blockIdx.x * 128;
    const int g = lane >> 2, tg = lane & 3;

    // A-fill mapping: thread = (slab 0..15, grp 0..15); rows 8grp..8grp+7
    const int slab = tid >> 4, grp = tid & 15;
    const int ss = slab & 3;
    const float* srcp = selsrc(ss, fgc, fgt, bgc, bgt);
    const size_t slabRowOff = ((size_t)(b * 27 + (slab >> 2)) * ROWS + row0) * 3;

    // ldmatrix.trans lane address pieces (A, [k][row] pitch 272)
    const uint32_t akl = (uint32_t)((lane & 7) + ((lane & 16) ? 8 : 0));
    const uint32_t arw = (uint32_t)(wm * 64 + ((lane & 8) ? 8 : 0));
    const int arow2 = wm * 64 + (lane & 15);
    const int hsel = lane >> 4;

    float acc[4][8][4];
    #pragma unroll
    for (int i = 0; i < 4; ++i)
        #pragma unroll
        for (int j = 0; j < 8; ++j)
            #pragma unroll
            for (int r = 0; r < 4; ++r) acc[i][j][r] = 0.f;

    // half-granular A fill: h = 0 -> rows 8grp..+3, h = 1 -> rows +4..+7
    auto ldXh = [&](int c, int h, float4* xv) {
        bool ok = (c < 6) || (slab < 12);
        if (ok) {
            const float4* base = (const float4*)(srcp + slabRowOff
                + (size_t)(4 * c) * (ROWS * 3)) + grp * 6 + 3 * h;
            xv[0] = __ldg(base); xv[1] = __ldg(base + 1); xv[2] = __ldg(base + 2);
        } else {
            xv[0] = xv[1] = xv[2] = make_float4(0.f, 0.f, 0.f, 0.f);
        }
    };
    auto stsXh = [&](const float4* xv, uint32_t bufoff, int h) {
        const float* f = (const float*)xv;   // 4 local rows x 3 cm
        uint32_t base = bufoff + (uint32_t)(slab * 3 * 272 + grp * 16 + h * 8);
        #pragma unroll
        for (int cm = 0; cm < 3; ++cm) {
            *(uint32_t*)(sm + base + cm * 272)     = packh2(f[cm],     f[3 + cm]);
            *(uint32_t*)(sm + base + cm * 272 + 4) = packh2(f[6 + cm], f[9 + cm]);
        }
    };
    auto ldB1 = [&](int ks, uint4* bf) {
        const uint4* bp = g_B1pk + ((ks * 4 + wn) * 4) * 32 + lane;
        #pragma unroll
        for (int gg = 0; gg < 4; ++gg) bf[gg] = __ldg(bp + gg * 32);
    };
    // one k16 step: 4 LDSM.trans + 32 MMA in two m-pair groups
    auto step1 = [&](uint32_t bufoff, int k0, const uint4* bf) {
        uint32_t addr = smb + bufoff + (uint32_t)((k0 + akl) * 272) + arw * 2;
        uint32_t ah2[2][4];
        ldmat4t(addr, ah2[0]);
        ldmat4t(addr + 32, ah2[1]);
        #pragma unroll
        for (int j = 0; j < 8; ++j) {
            uint32_t b0 = (j & 1) ? bf[j >> 1].z : bf[j >> 1].x;
            uint32_t b1 = (j & 1) ? bf[j >> 1].w : bf[j >> 1].y;
            mma16816(acc[0][j], ah2[0], b0, b1);
            mma16816(acc[1][j], ah2[1], b0, b1);
        }
        ldmat4t(addr + 64, ah2[0]);
        ldmat4t(addr + 96, ah2[1]);
        #pragma unroll
        for (int j = 0; j < 8; ++j) {
            uint32_t b0 = (j & 1) ? bf[j >> 1].z : bf[j >> 1].x;
            uint32_t b1 = (j & 1) ? bf[j >> 1].w : bf[j >> 1].y;
            mma16816(acc[2][j], ah2[0], b0, b1);
            mma16816(acc[3][j], ah2[1], b0, b1);
        }
    };

    // ---- stage-1 prologue: chunk 0 -> buf 0 ----
    uint4 bfA[4], bfB[4];
    ldB1(0, bfA);
    {
        float4 xv[3];
        ldXh(0, 0, xv); stsXh(xv, A1F(0), 0);
        ldXh(0, 1, xv); stsXh(xv, A1F(0), 1);
    }
    __syncthreads();

    // ---- stage 1: 7 chunks of k48 (21 k16 steps), pair-unrolled ----
    float4 xv[3];
    for (int cp = 0; cp < 3; ++cp) {
        const int c0 = 2 * cp;
        const int ks = 6 * cp;
        ldXh(c0 + 1, 0, xv);
        ldB1(ks + 1, bfB); step1(A1F(0), 0,  bfA);
        stsXh(xv, A1F(1), 0);
        ldXh(c0 + 1, 1, xv);
        ldB1(ks + 2, bfA); step1(A1F(0), 16, bfB);
        stsXh(xv, A1F(1), 1);
        ldB1(ks + 3, bfB); step1(A1F(0), 32, bfA);
        __syncthreads();
        ldXh(c0 + 2, 0, xv);
        ldB1(ks + 4, bfA); step1(A1F(1), 0,  bfB);
        stsXh(xv, A1F(0), 0);
        ldXh(c0 + 2, 1, xv);
        ldB1(ks + 5, bfB); step1(A1F(1), 16, bfA);
        stsXh(xv, A1F(0), 1);
        ldB1(ks + 6, bfA); step1(A1F(1), 32, bfB);
        __syncthreads();
    }
    {   // tail chunk 6 in buf 0: k16 steps 18,19,20
        ldB1(19, bfB); step1(A1F(0), 0,  bfA);
        ldB1(20, bfA); step1(A1F(0), 16, bfB);
        step1(A1F(0), 32, bfA);
    }
    __syncthreads();

    // ---- epilogue 1: bias + relu + fp16 -> C1 smem (pitch 528B) ----
    #pragma unroll
    for (int i = 0; i < 4; ++i) {
        int m0 = wm * 64 + i * 16 + g;
        #pragma unroll
        for (int j = 0; j < 8; ++j) {
            int n = wn * 64 + j * 8 + tg * 2;
            float bn0 = b1[n], bn1 = b1[n + 1];
            float x0 = fmaxf(acc[i][j][0] + bn0, 0.f);
            float x1 = fmaxf(acc[i][j][1] + bn1, 0.f);
            float x2 = fmaxf(acc[i][j][2] + bn0, 0.f);
            float x3 = fmaxf(acc[i][j][3] + bn1, 0.f);
            *(uint32_t*)(sm + C1H + m0 * 528 + n * 2)       = packh2(x0, x1);
            *(uint32_t*)(sm + C1H + (m0 + 8) * 528 + n * 2) = packh2(x2, x3);
        }
    }
    __syncthreads();

    // ---- stage 2: C2 = C1 @ W2, 16 chunks, barrier-free, B prefetch ----
    float acc2[4][4][4];
    #pragma unroll
    for (int i = 0; i < 4; ++i)
        #pragma unroll
        for (int j = 0; j < 4; ++j)
            #pragma unroll
            for (int r = 0; r < 4; ++r) acc2[i][j][r] = 0.f;

    auto ldB2 = [&](int c, uint4* bf) {
        const uint4* bp = g_B2pk + ((c * 4 + wn) * 2) * 32 + lane;
        bf[0] = __ldg(bp);
        bf[1] = __ldg(bp + 32);
    };
    auto step2 = [&](int c, const uint4* bf) {
        uint32_t aAddr = smb + C1H + (uint32_t)(arow2 * 528 + c * 32 + hsel * 16);
        uint32_t ah2[2][4];
        ldmat4(aAddr, ah2[0]);
        ldmat4(aAddr + 16 * 528, ah2[1]);
        #pragma unroll
        for (int j = 0; j < 4; ++j) {
            uint32_t b0 = (j & 1) ? bf[j >> 1].z : bf[j >> 1].x;
            uint32_t b1r = (j & 1) ? bf[j >> 1].w : bf[j >> 1].y;
            mma16816(acc2[0][j], ah2[0], b0, b1r);
            mma16816(acc2[1][j], ah2[1], b0, b1r);
        }
        ldmat4(aAddr + 32 * 528, ah2[0]);
        ldmat4(aAddr + 48 * 528, ah2[1]);
        #pragma unroll
        for (int j = 0; j < 4; ++j) {
            uint32_t b0 = (j & 1) ? bf[j >> 1].z : bf[j >> 1].x;
            uint32_t b1r = (j & 1) ? bf[j >> 1].w : bf[j >> 1].y;
            mma16816(acc2[2][j], ah2[0], b0, b1r);
            mma16816(acc2[3][j], ah2[1], b0, b1r);
        }
    };

    uint4 b2A[2], b2B[2];
    ldB2(0, b2A);
    for (int cp = 0; cp < 8; ++cp) {
        const int c0 = 2 * cp, c1 = c0 + 1;
        ldB2(c1, b2B);
        step2(c0, b2A);
        if (c1 < 15) ldB2(c1 + 1, b2A);
        step2(c1, b2B);
    }
    __syncthreads();   // all warps done reading C1 before staging overwrites it

    // ---- epilogue 2: + b2 -> fp16 staging smem [z][m] (pitch 272B) ----
    #pragma unroll
    for (int i = 0; i < 4; ++i) {
        int m0 = wm * 64 + i * 16 + g;
        #pragma unroll
        for (int j = 0; j < 4; ++j) {
            int z = wn * 32 + j * 8 + tg * 2;
            float bz0 = b2[z], bz1 = b2[z + 1];
            *(__half*)(sm + STG + z * 272 + m0 * 2)             = __float2half_rn(acc2[i][j][0] + bz0);
            *(__half*)(sm + STG + (z + 1) * 272 + m0 * 2)       = __float2half_rn(acc2[i][j][1] + bz1);
            *(__half*)(sm + STG + z * 272 + (m0 + 8) * 2)       = __float2half_rn(acc2[i][j][2] + bz0);
            *(__half*)(sm + STG + (z + 1) * 272 + (m0 + 8) * 2) = __float2half_rn(acc2[i][j][3] + bz1);
        }
    }
    __syncthreads();

    #pragma unroll
    for (int e = tid; e < 2048; e += 256) {
        int z = e >> 4, q = e & 15;
        uint4 v = *(uint4*)(sm + STG + z * 272 + q * 16);
        *(uint4*)(g_Hh + ((size_t)b * 128 + z) * ROWS + row0 + q * 8) = v;
    }
}

// ============================================================
// invariant pooling + vector_log (CTA per (b,z)), 256 threads
// ============================================================
__global__ void pool_kernel()
{
    extern __shared__ float S[];
    const int tid = threadIdx.x;          // 256
    const int bz = blockIdx.x;
    const __half2* src = (const __half2*)(g_Hh + (size_t)bz * ROWS);
    for (int e = tid; e < 8192; e += 256) {
        float2 v = __half22float2(src[e]);
        int row = e >> 6, col = (e & 63) * 2;
        S[row * 129 + col] = v.x;
        S[row * 129 + col + 1] = v.y;
    }
    __syncthreads();
    const int a = tid >> 1, h = tid & 1;
    const float* rowp = S + a * 129 + h * 64;
    float r = 0.f, cc = 0.f, p4 = 0.f, p5 = 0.f;
    #pragma unroll 4
    for (int bb = 0; bb < 64; ++bb) {
        float xab = rowp[bb];
        float xba = S[(h * 64 + bb) * 129 + a];
        r += xab; cc += xba;
        p4 = fmaf(xab, xab, p4);
        p5 = fmaf(xab, xba, p5);
    }
    float d = ((a >> 6) == h) ? S[a * 129 + a] : 0.f;
    float rf = r + __shfl_xor_sync(0xffffffff, r, 1);
    float cf = cc + __shfl_xor_sync(0xffffffff, cc, 1);
    float dd = d + __shfl_xor_sync(0xffffffff, d, 1);
    float vals[8];
    vals[0] = d;
    vals[1] = r;
    vals[2] = d * d;
    vals[3] = (h == 0) ? dd * rf : 0.f;
    vals[4] = p4;
    vals[5] = p5;
    vals[6] = (h == 0) ? rf * rf : 0.f;
    vals[7] = (h == 0) ? rf * cf : 0.f;
    __syncthreads();
    float* red = S;
    #pragma unroll
    for (int q = 0; q < 8; ++q) {
        float v = vals[q];
        #pragma unroll
        for (int off = 16; off > 0; off >>= 1)
            v += __shfl_down_sync(0xffffffff, v, off);
        if ((tid & 31) == 0) red[(tid >> 5) * 8 + q] = v;
    }
    __syncthreads();
    if (tid < 8) {
        float hsum = 0.f;
        #pragma unroll
        for (int w = 0; w < 8; ++w) hsum += red[w * 8 + tid];
        const float denom[8] = {128.f, 16384.f, 128.f, 16384.f,
                                16384.f, 16384.f, 2097152.f, 2097152.f};
        float p = hsum / denom[tid];
        float vl = copysignf(log1pf(fabsf(p)) * 0.1f, p);
        g_P[(bz >> 7) * 1024 + tid * 128 + (bz & 127)] = vl;
    }
}

// ============================================================
// mlp2a: split-K partials (grid 16 x 32)
// ============================================================
__global__ void mlp2a_kernel(const float* __restrict__ W3)
{
    const int r = blockIdx.x, h = blockIdx.y;
    const int n = threadIdx.x;               // 256
    const float* p = g_P + r * 1024 + h * 32;
    const float* w = W3 + (size_t)h * 32 * 256;
    float acc = 0.f;
    #pragma unroll 8
    for (int k = 0; k < 32; ++k)
        acc = fmaf(p[k], w[k * 256 + n], acc);
    g_part[(r * 32 + h) * 256 + n] = acc;
}

// ============================================================
// mlp2b: reduce partials + bias/relu + final GEMV + tanh
// ============================================================
__global__ void mlp2b_kernel(const float* __restrict__ b3,
                             const float* __restrict__ W4, const float* __restrict__ b4,
                             float* __restrict__ out)
{
    __shared__ float H2[16 * 256];
    const int tid = threadIdx.x;              // 512
    for (int e = tid; e < 4096; e += 512) {
        int r = e >> 8, n = e & 255;
        float s = 0.f;
        #pragma unroll
        for (int h = 0; h < 32; ++h) s += g_part[(r * 32 + h) * 256 + n];
        H2[e] = fmaxf(s + b3[n], 0.f);
    }
    __syncthreads();
    const int o = tid >> 4, g = tid & 15;
    const int r = o >> 1, c = o & 1;
    float s = 0.f;
    #pragma unroll 4
    for (int k = g; k < 256; k += 16)
        s = fmaf(H2[r * 256 + k], W4[k * 2 + c], s);
    s += __shfl_down_sync(0xffffffff, s, 8, 16);
    s += __shfl_down_sync(0xffffffff, s, 4, 16);
    s += __shfl_down_sync(0xffffffff, s, 2, 16);
    s += __shfl_down_sync(0xffffffff, s, 1, 16);
    if (g == 0) out[o] = tanhf(s + b4[c]) * 8.0f;
}

// ============================================================
extern "C" void kernel_launch(void* const* d_in, const int* in_sizes, int n_in,
                              void* d_out, int out_size)
{
    const float* fgc = (const float*)d_in[0];
    const float* fgt = (const float*)d_in[1];
    const float* bgc = (const float*)d_in[2];
    const float* bgt = (const float*)d_in[3];
    const float* W1  = (const float*)d_in[4];
    const float* b1  = (const float*)d_in[5];
    const float* W2  = (const float*)d_in[6];
    const float* b2  = (const float*)d_in[7];
    const float* W3  = (const float*)d_in[8];
    const float* b3  = (const float*)d_in[9];
    const float* W4  = (const float*)d_in[10];
    const float* b4  = (const float*)d_in[11];
    float* out = (float*)d_out;

    cudaFuncSetAttribute(gemm_mma_kernel, cudaFuncAttributeMaxDynamicSharedMemorySize, SMEM_TOTAL);
    cudaFuncSetAttribute(pool_kernel,     cudaFuncAttributeMaxDynamicSharedMemorySize, 128 * 129 * 4);

    dummy_a_kernel<<<1, 32>>>();
    dummy_b_kernel<<<1, 32>>>();
    prep_w_kernel<<<63, 256>>>(W1, W2);
    gemm_mma_kernel<<<dim3(128, NB), 256, SMEM_TOTAL>>>(fgc, fgt, bgc, bgt, b1, b2);
    pool_kernel<<<NB * 128, 256, 128 * 129 * 4>>>();
    mlp2a_kernel<<<dim3(16, 32), 256>>>(W3);
    mlp2b_kernel<<<1, 512>>>(b3, W4, b4, out);
}

// round 16
// speedup vs baseline: 1.1835x; 1.1835x over previous
#include <cuda_runtime.h>
#include <cuda_fp16.h>
#include <math.h>
#include <stdint.h>

#define NB 16
#define ROWS 16384

// ---------------- device scratch ----------------
__device__ __align__(16) __half g_Hh[(size_t)NB * 128 * ROWS];  // [b][z][row] fp16
__device__ float g_P[NB * 1024];
__device__ float g_part[NB * 32 * 256];
__device__ __align__(16) uint4 g_B1pk[21 * 4 * 4 * 32];  // [ks][wn][g][lane]
__device__ __align__(16) uint4 g_B2pk[16 * 4 * 2 * 32];  // [c][wn][g][lane]

// ---------------- smem layout (bytes), 64-row CTA ----------------
#define C1H 0                           // 64 x 264 halves (pitch 528B) = 33792
#define A1F(bi) (33792 + (bi) * 6912)   // A tile [k48][row64] fp16, pitch 144B
#define STG 0                           // epilogue-2 staging reuses C1
#define SMEM_TOTAL 47616

// ---------------- helpers ----------------
__device__ __forceinline__ uint32_t smem_u32(const void* p) {
    uint32_t a;
    asm("{ .reg .u64 t; cvta.to.shared.u64 t, %1; cvt.u32.u64 %0, t; }" : "=r"(a) : "l"(p));
    return a;
}
__device__ __forceinline__ void ldmat4(uint32_t addr, uint32_t r[4]) {
    asm volatile("ldmatrix.sync.aligned.m8n8.x4.shared.b16 {%0,%1,%2,%3}, [%4];"
        : "=r"(r[0]), "=r"(r[1]), "=r"(r[2]), "=r"(r[3]) : "r"(addr) : "memory");
}
__device__ __forceinline__ void ldmat4t(uint32_t addr, uint32_t r[4]) {
    asm volatile("ldmatrix.sync.aligned.m8n8.x4.trans.shared.b16 {%0,%1,%2,%3}, [%4];"
        : "=r"(r[0]), "=r"(r[1]), "=r"(r[2]), "=r"(r[3]) : "r"(addr) : "memory");
}
__device__ __forceinline__ void mma16816(float d[4], const uint32_t a[4],
                                         uint32_t b0, uint32_t b1) {
    asm volatile("mma.sync.aligned.m16n8k16.row.col.f32.f16.f16.f32 "
        "{%0,%1,%2,%3}, {%4,%5,%6,%7}, {%8,%9}, {%0,%1,%2,%3};"
        : "+f"(d[0]), "+f"(d[1]), "+f"(d[2]), "+f"(d[3])
        : "r"(a[0]), "r"(a[1]), "r"(a[2]), "r"(a[3]), "r"(b0), "r"(b1));
}
__device__ __forceinline__ uint32_t packh2(float x, float y) {
    __half2 h = __floats2half2_rn(x, y);
    return *(uint32_t*)&h;
}
__device__ __forceinline__ const float* selsrc(int s, const float* a, const float* b,
                                               const float* c, const float* d) {
    return s == 0 ? a : (s == 1 ? b : (s == 2 ? c : d));
}

// ============================================================
// prep: pack W1/W2 into per-lane mma B-fragment order.
// ============================================================
__global__ void prep_w_kernel(const float* __restrict__ W1, const float* __restrict__ W2)
{
    int idx = blockIdx.x * 256 + threadIdx.x;
    if (idx < 21 * 4 * 4 * 32) {
        int lane = idx & 31, g = (idx >> 5) & 3, wn = (idx >> 7) & 3, c = idx >> 9;
        int n0 = wn * 64 + (2 * g) * 8 + (lane >> 2);
        int n1 = n0 + 8;
        int kb = c * 16 + 2 * (lane & 3);
        auto f = [&](int k, int n) -> float { return (k < 324) ? W1[k * 256 + n] : 0.f; };
        uint4 v;
        v.x = packh2(f(kb, n0),     f(kb + 1, n0));
        v.y = packh2(f(kb + 8, n0), f(kb + 9, n0));
        v.z = packh2(f(kb, n1),     f(kb + 1, n1));
        v.w = packh2(f(kb + 8, n1), f(kb + 9, n1));
        g_B1pk[idx] = v;
    } else {
        int m = idx - 21 * 4 * 4 * 32;
        if (m < 16 * 4 * 2 * 32) {
            int lane = m & 31, g = (m >> 5) & 1, wn = (m >> 6) & 3, c = m >> 8;
            int n0 = wn * 32 + (2 * g) * 8 + (lane >> 2);
            int n1 = n0 + 8;
            int kb = c * 16 + 2 * (lane & 3);
            uint4 v;
            v.x = packh2(W2[kb * 128 + n0],       W2[(kb + 1) * 128 + n0]);
            v.y = packh2(W2[(kb + 8) * 128 + n0], W2[(kb + 9) * 128 + n0]);
            v.z = packh2(W2[kb * 128 + n1],       W2[(kb + 1) * 128 + n1]);
            v.w = packh2(W2[(kb + 8) * 128 + n1], W2[(kb + 9) * 128 + n1]);
            g_B2pk[m] = v;
        }
    }
}

// ============================================================
// fused GEMM1 -> ReLU -> GEMM2, fp16 MMA
// CTA: 256 threads (2M x 4N warps), 64 rows, 2 CTAs/SM. grid (256, 16).
// Stage-1 A: contiguous 768B slab loads (48-k chunks = 4 t-slices),
//            [k][row] smem pitch 144B, ldmatrix.x4.trans.
// B: LDG.128 pre-packed fragments, register-prefetched 1 step ahead.
// ============================================================
__global__ void __launch_bounds__(256, 2) gemm_mma_kernel(
    const float* __restrict__ fgc, const float* __restrict__ fgt,
    const float* __restrict__ bgc, const float* __restrict__ bgt,
    const float* __restrict__ b1, const float* __restrict__ b2)
{
    extern __shared__ char sm[];
    const uint32_t smb = smem_u32(sm);
    const int tid = threadIdx.x, lane = tid & 31, warp = tid >> 5;
    const int wm = warp & 1, wn = warp >> 1;          // 2 x 4
    const int b = blockIdx.y;
    const int row0 = blockIdx.x * 64;
    const int g = lane >> 2, tg = lane & 3;

    const int arow = wm * 32 + (lane & 15);
    const int hsel = lane >> 4;

    // A-fill mapping: thread = (slab 0..15, grp 0..15); rows 4grp..4grp+3, 12 floats
    const int slab = tid >> 4, grp = tid & 15;
    const int ss = slab & 3;
    const float* srcp = selsrc(ss, fgc, fgt, bgc, bgt);
    const size_t slabRowOff = ((size_t)(b * 27 + (slab >> 2)) * ROWS + row0) * 3;

    // ldmatrix.trans lane address pieces (A, [k][row] pitch 144)
    const uint32_t akl = (uint32_t)((lane & 7) + ((lane & 16) ? 8 : 0));
    const uint32_t arw = (uint32_t)(wm * 32 + ((lane & 8) ? 8 : 0));

    float acc[2][8][4];
    #pragma unroll
    for (int i = 0; i < 2; ++i)
        #pragma unroll
        for (int j = 0; j < 8; ++j)
            #pragma unroll
            for (int r = 0; r < 4; ++r) acc[i][j][r] = 0.f;

    auto ldX = [&](int c, float4* xv) {
        bool ok = (c < 6) || (slab < 12);
        if (ok) {
            const float4* base = (const float4*)(srcp + slabRowOff
                + (size_t)(4 * c) * (ROWS * 3)) + grp * 3;
            xv[0] = __ldg(base); xv[1] = __ldg(base + 1); xv[2] = __ldg(base + 2);
        } else {
            xv[0] = xv[1] = xv[2] = make_float4(0.f, 0.f, 0.f, 0.f);
        }
    };
    auto stsX = [&](const float4* xv, uint32_t bufoff) {
        const float* f = (const float*)xv;   // rows 4grp..+3, cm 0..2 interleaved
        uint32_t base = bufoff + (uint32_t)(slab * 3 * 144 + grp * 8);
        #pragma unroll
        for (int cm = 0; cm < 3; ++cm) {
            *(uint32_t*)(sm + base + cm * 144)     = packh2(f[cm],     f[cm + 3]);
            *(uint32_t*)(sm + base + cm * 144 + 4) = packh2(f[cm + 6], f[cm + 9]);
        }
    };
    auto ldsmA1 = [&](uint32_t bufoff, int k0, uint32_t ah[2][4]) {
        uint32_t addr = smb + bufoff + (uint32_t)((k0 + akl) * 144) + arw * 2;
        ldmat4t(addr, ah[0]);
        ldmat4t(addr + 32, ah[1]);       // +16 rows
    };
    auto ldB1 = [&](int ks, uint4* bf) {
        const uint4* bp = g_B1pk + ((ks * 4 + wn) * 4) * 32 + lane;
        #pragma unroll
        for (int gg = 0; gg < 4; ++gg) bf[gg] = __ldg(bp + gg * 32);
    };
    auto mmaS1 = [&](const uint32_t ah[2][4], const uint4* bf) {
        #pragma unroll
        for (int j = 0; j < 8; ++j) {
            uint32_t b0 = (j & 1) ? bf[j >> 1].z : bf[j >> 1].x;
            uint32_t b1 = (j & 1) ? bf[j >> 1].w : bf[j >> 1].y;
            mma16816(acc[0][j], ah[0], b0, b1);
            mma16816(acc[1][j], ah[1], b0, b1);
        }
    };

    // ---- stage-1 prologue: chunk 0 -> buf 0 ----
    uint4 bfA[4], bfB[4];
    ldB1(0, bfA);
    {
        float4 xv[3];
        ldX(0, xv);
        stsX(xv, A1F(0));
    }
    __syncthreads();

    // ---- stage 1: 7 chunks of k48 (21 k16 steps), pair-unrolled ----
    float4 xv[3];
    for (int cp = 0; cp < 3; ++cp) {
        const int c0 = 2 * cp;          // buf 0
        const int ks = 6 * cp;
        ldX(c0 + 1, xv);
        uint32_t ah[2][4];
        ldB1(ks + 1, bfB); ldsmA1(A1F(0), 0,  ah); mmaS1(ah, bfA);
        ldB1(ks + 2, bfA); ldsmA1(A1F(0), 16, ah); mmaS1(ah, bfB);
        stsX(xv, A1F(1));
        ldB1(ks + 3, bfB); ldsmA1(A1F(0), 32, ah); mmaS1(ah, bfA);
        __syncthreads();                // buf1 ready, buf0 free
        ldX(c0 + 2, xv);
        ldB1(ks + 4, bfA); ldsmA1(A1F(1), 0,  ah); mmaS1(ah, bfB);
        ldB1(ks + 5, bfB); ldsmA1(A1F(1), 16, ah); mmaS1(ah, bfA);
        stsX(xv, A1F(0));
        ldB1(ks + 6, bfA); ldsmA1(A1F(1), 32, ah); mmaS1(ah, bfB);
        __syncthreads();                // buf0 ready (chunk c0+2)
    }
    {   // tail chunk 6 in buf 0: steps 18,19,20
        uint32_t ah[2][4];
        ldB1(19, bfB); ldsmA1(A1F(0), 0,  ah); mmaS1(ah, bfA);
        ldB1(20, bfA); ldsmA1(A1F(0), 16, ah); mmaS1(ah, bfB);
        ldsmA1(A1F(0), 32, ah); mmaS1(ah, bfA);
    }

    // ---- epilogue 1: bias + relu + fp16 -> C1 smem (pitch 528B) ----
    __syncthreads();
    #pragma unroll
    for (int i = 0; i < 2; ++i) {
        int m0 = wm * 32 + i * 16 + g;
        #pragma unroll
        for (int j = 0; j < 8; ++j) {
            int n = wn * 64 + j * 8 + tg * 2;
            float bn0 = b1[n], bn1 = b1[n + 1];
            float x0 = fmaxf(acc[i][j][0] + bn0, 0.f);
            float x1 = fmaxf(acc[i][j][1] + bn1, 0.f);
            float x2 = fmaxf(acc[i][j][2] + bn0, 0.f);
            float x3 = fmaxf(acc[i][j][3] + bn1, 0.f);
            *(uint32_t*)(sm + C1H + m0 * 528 + n * 2)       = packh2(x0, x1);
            *(uint32_t*)(sm + C1H + (m0 + 8) * 528 + n * 2) = packh2(x2, x3);
        }
    }
    __syncthreads();

    // ---- stage 2: C2 = C1 @ W2, 16 chunks, barrier-free, B prefetch ----
    float acc2[2][4][4];
    #pragma unroll
    for (int i = 0; i < 2; ++i)
        #pragma unroll
        for (int j = 0; j < 4; ++j)
            #pragma unroll
            for (int r = 0; r < 4; ++r) acc2[i][j][r] = 0.f;

    auto ldB2 = [&](int c, uint4* bf) {
        const uint4* bp = g_B2pk + ((c * 4 + wn) * 2) * 32 + lane;
        bf[0] = __ldg(bp);
        bf[1] = __ldg(bp + 32);
    };
    auto mmaS2 = [&](const uint32_t ah[2][4], const uint4* bf) {
        #pragma unroll
        for (int j = 0; j < 4; ++j) {
            uint32_t b0 = (j & 1) ? bf[j >> 1].z : bf[j >> 1].x;
            uint32_t b1r = (j & 1) ? bf[j >> 1].w : bf[j >> 1].y;
            mma16816(acc2[0][j], ah[0], b0, b1r);
            mma16816(acc2[1][j], ah[1], b0, b1r);
        }
    };

    const int nrow2 = wn * 32 + (lane & 15);
    (void)nrow2;
    uint4 b2A[2], b2B[2];
    ldB2(0, b2A);
    for (int cp = 0; cp < 8; ++cp) {
        const int c0 = 2 * cp, c1 = c0 + 1;
        ldB2(c1, b2B);
        {
            uint32_t ah[2][4];
            uint32_t aAddr = smb + C1H + (uint32_t)(arow * 528 + c0 * 32 + hsel * 16);
            ldmat4(aAddr, ah[0]);
            ldmat4(aAddr + 16 * 528, ah[1]);
            mmaS2(ah, b2A);
        }
        if (c1 < 15) ldB2(c1 + 1, b2A);
        {
            uint32_t ah[2][4];
            uint32_t aAddr = smb + C1H + (uint32_t)(arow * 528 + c1 * 32 + hsel * 16);
            ldmat4(aAddr, ah[0]);
            ldmat4(aAddr + 16 * 528, ah[1]);
            mmaS2(ah, b2B);
        }
    }
    __syncthreads();   // all warps done reading C1 before staging overwrites it

    // ---- epilogue 2: + b2 -> fp16 staging smem [z][m] (pitch 144B) ----
    #pragma unroll
    for (int i = 0; i < 2; ++i) {
        int m0 = wm * 32 + i * 16 + g;
        #pragma unroll
        for (int j = 0; j < 4; ++j) {
            int z = wn * 32 + j * 8 + tg * 2;
            float bz0 = b2[z], bz1 = b2[z + 1];
            *(__half*)(sm + STG + z * 144 + m0 * 2)             = __float2half_rn(acc2[i][j][0] + bz0);
            *(__half*)(sm + STG + (z + 1) * 144 + m0 * 2)       = __float2half_rn(acc2[i][j][1] + bz1);
            *(__half*)(sm + STG + z * 144 + (m0 + 8) * 2)       = __float2half_rn(acc2[i][j][2] + bz0);
            *(__half*)(sm + STG + (z + 1) * 144 + (m0 + 8) * 2) = __float2half_rn(acc2[i][j][3] + bz1);
        }
    }
    __syncthreads();

    #pragma unroll
    for (int e = tid; e < 1024; e += 256) {
        int z = e >> 3, q = e & 7;
        uint4 v = *(uint4*)(sm + STG + z * 144 + q * 16);
        *(uint4*)(g_Hh + ((size_t)b * 128 + z) * ROWS + row0 + q * 8) = v;
    }
}

// ============================================================
// invariant pooling + vector_log (CTA per (b,z)), 256 threads
// ============================================================
__global__ void pool_kernel()
{
    extern __shared__ float S[];
    const int tid = threadIdx.x;          // 256
    const int bz = blockIdx.x;
    const __half2* src = (const __half2*)(g_Hh + (size_t)bz * ROWS);
    for (int e = tid; e < 8192; e += 256) {
        float2 v = __half22float2(src[e]);
        int row = e >> 6, col = (e & 63) * 2;
        S[row * 129 + col] = v.x;
        S[row * 129 + col + 1] = v.y;
    }
    __syncthreads();
    const int a = tid >> 1, h = tid & 1;
    const float* rowp = S + a * 129 + h * 64;
    float r = 0.f, cc = 0.f, p4 = 0.f, p5 = 0.f;
    #pragma unroll 4
    for (int bb = 0; bb < 64; ++bb) {
        float xab = rowp[bb];
        float xba = S[(h * 64 + bb) * 129 + a];
        r += xab; cc += xba;
        p4 = fmaf(xab, xab, p4);
        p5 = fmaf(xab, xba, p5);
    }
    float d = ((a >> 6) == h) ? S[a * 129 + a] : 0.f;
    float rf = r + __shfl_xor_sync(0xffffffff, r, 1);
    float cf = cc + __shfl_xor_sync(0xffffffff, cc, 1);
    float dd = d + __shfl_xor_sync(0xffffffff, d, 1);
    float vals[8];
    vals[0] = d;
    vals[1] = r;
    vals[2] = d * d;
    vals[3] = (h == 0) ? dd * rf : 0.f;
    vals[4] = p4;
    vals[5] = p5;
    vals[6] = (h == 0) ? rf * rf : 0.f;
    vals[7] = (h == 0) ? rf * cf : 0.f;
    __syncthreads();
    float* red = S;
    #pragma unroll
    for (int q = 0; q < 8; ++q) {
        float v = vals[q];
        #pragma unroll
        for (int off = 16; off > 0; off >>= 1)
            v += __shfl_down_sync(0xffffffff, v, off);
        if ((tid & 31) == 0) red[(tid >> 5) * 8 + q] = v;
    }
    __syncthreads();
    if (tid < 8) {
        float hsum = 0.f;
        #pragma unroll
        for (int w = 0; w < 8; ++w) hsum += red[w * 8 + tid];
        const float denom[8] = {128.f, 16384.f, 128.f, 16384.f,
                                16384.f, 16384.f, 2097152.f, 2097152.f};
        float p = hsum / denom[tid];
        float vl = copysignf(log1pf(fabsf(p)) * 0.1f, p);
        g_P[(bz >> 7) * 1024 + tid * 128 + (bz & 127)] = vl;
    }
}

// ============================================================
// mlp2a: split-K partials (grid 16 x 32)
// ============================================================
__global__ void mlp2a_kernel(const float* __restrict__ W3)
{
    const int r = blockIdx.x, h = blockIdx.y;
    const int n = threadIdx.x;               // 256
    const float* p = g_P + r * 1024 + h * 32;
    const float* w = W3 + (size_t)h * 32 * 256;
    float acc = 0.f;
    #pragma unroll 8
    for (int k = 0; k < 32; ++k)
        acc = fmaf(p[k], w[k * 256 + n], acc);
    g_part[(r * 32 + h) * 256 + n] = acc;
}

// ============================================================
// mlp2b: reduce partials + bias/relu + final GEMV + tanh
// ============================================================
__global__ void mlp2b_kernel(const float* __restrict__ b3,
                             const float* __restrict__ W4, const float* __restrict__ b4,
                             float* __restrict__ out)
{
    __shared__ float H2[16 * 256];
    const int tid = threadIdx.x;              // 512
    for (int e = tid; e < 4096; e += 512) {
        int r = e >> 8, n = e & 255;
        float s = 0.f;
        #pragma unroll
        for (int h = 0; h < 32; ++h) s += g_part[(r * 32 + h) * 256 + n];
        H2[e] = fmaxf(s + b3[n], 0.f);
    }
    __syncthreads();
    const int o = tid >> 4, g = tid & 15;
    const int r = o >> 1, c = o & 1;
    float s = 0.f;
    #pragma unroll 4
    for (int k = g; k < 256; k += 16)
        s = fmaf(H2[r * 256 + k], W4[k * 2 + c], s);
    s += __shfl_down_sync(0xffffffff, s, 8, 16);
    s += __shfl_down_sync(0xffffffff, s, 4, 16);
    s += __shfl_down_sync(0xffffffff, s, 2, 16);
    s += __shfl_down_sync(0xffffffff, s, 1, 16);
    if (g == 0) out[o] = tanhf(s + b4[c]) * 8.0f;
}

// ============================================================
extern "C" void kernel_launch(void* const* d_in, const int* in_sizes, int n_in,
                              void* d_out, int out_size)
{
    const float* fgc = (const float*)d_in[0];
    const float* fgt = (const float*)d_in[1];
    const float* bgc = (const float*)d_in[2];
    const float* bgt = (const float*)d_in[3];
    const float* W1  = (const float*)d_in[4];
    const float* b1  = (const float*)d_in[5];
    const float* W2  = (const float*)d_in[6];
    const float* b2  = (const float*)d_in[7];
    const float* W3  = (const float*)d_in[8];
    const float* b3  = (const float*)d_in[9];
    const float* W4  = (const float*)d_in[10];
    const float* b4  = (const float*)d_in[11];
    float* out = (float*)d_out;

    cudaFuncSetAttribute(gemm_mma_kernel, cudaFuncAttributeMaxDynamicSharedMemorySize, SMEM_TOTAL);
    cudaFuncSetAttribute(pool_kernel,     cudaFuncAttributeMaxDynamicSharedMemorySize, 128 * 129 * 4);

    prep_w_kernel<<<63, 256>>>(W1, W2);
    gemm_mma_kernel<<<dim3(256, NB), 256, SMEM_TOTAL>>>(fgc, fgt, bgc, bgt, b1, b2);
    pool_kernel<<<NB * 128, 256, 128 * 129 * 4>>>();
    mlp2a_kernel<<<dim3(16, 32), 256>>>(W3);
    mlp2b_kernel<<<1, 512>>>(b3, W4, b4, out);
}